// round 14
// baseline (speedup 1.0000x reference)
#include <cuda_runtime.h>
#include <cuda_fp16.h>
#include <math.h>
#include <stdint.h>

// Problem constants (fixed shapes per reference)
#define N_D   4096
#define N_M   8192
#define NN    12288          // N_D + N_M
#define EE    196608
#define KHOP  4
#define HIDD  512
#define LDF   2560           // HID*(K+1)

// ---------------- device scratch ------------------------------------------
__device__ int   g_deg[NN];
__device__ float g_norm[NN];
__device__ int   g_offs[NN + 1];
__device__ int   g_cursor[NN];
__device__ int   g_csr_src[EE];
__device__ float g_csr_w[EE];
__device__ __half g_hh[(size_t)NN * HIDD];                // [N, 512] fp16 h
__device__ __half g_Fh[(size_t)NN * LDF];                 // feat, fp16
__device__ __half g_Bt[(size_t)512 * (N_D + N_M + LDF)];  // W^T fp16 (d|m|f)
__device__ __half g_Ah[(size_t)N_D * N_D + (size_t)N_M * N_M]; // fp16 sims (d|m)
__device__ __half g_Pd[(size_t)8 * N_D * HIDD];           // d split-K partials (x8)
__device__ __half g_Pm[(size_t)2 * N_M * HIDD];           // m split-K partials (x2)
__device__ __half g_Pf[(size_t)2 * NN * HIDD];            // f split-K partials (x2)

// ---------------- PTX helpers (plain sm_103-safe) ---------------------------
__device__ __forceinline__ uint32_t smem_u32(const void* p) {
    uint32_t a;
    asm("{ .reg .u64 t; cvta.to.shared.u64 t, %1; cvt.u32.u64 %0, t; }"
        : "=r"(a) : "l"(p));
    return a;
}

__device__ __forceinline__ void cpasync16(uint32_t dst, const void* src) {
    asm volatile("cp.async.cg.shared.global [%0], [%1], 16;" :: "r"(dst), "l"(src));
}
__device__ __forceinline__ void cp_commit() {
    asm volatile("cp.async.commit_group;" ::: "memory");
}
template <int N>
__device__ __forceinline__ void cp_wait() {
    asm volatile("cp.async.wait_group %0;" :: "n"(N) : "memory");
}

__device__ __forceinline__ void ldsm_x4(uint32_t addr, uint32_t& r0, uint32_t& r1,
                                        uint32_t& r2, uint32_t& r3) {
    asm volatile("ldmatrix.sync.aligned.m8n8.x4.shared.b16 {%0,%1,%2,%3}, [%4];"
                 : "=r"(r0), "=r"(r1), "=r"(r2), "=r"(r3) : "r"(addr));
}

__device__ __forceinline__ void mma16816(float* c, const uint32_t* a, const uint32_t* b) {
    asm volatile(
        "mma.sync.aligned.m16n8k16.row.col.f32.f16.f16.f32 "
        "{%0,%1,%2,%3}, {%4,%5,%6,%7}, {%8,%9}, {%0,%1,%2,%3};"
        : "+f"(c[0]), "+f"(c[1]), "+f"(c[2]), "+f"(c[3])
        : "r"(a[0]), "r"(a[1]), "r"(a[2]), "r"(a[3]), "r"(b[0]), "r"(b[1]));
}

// ---------------- graph-prep kernels ---------------------------------------
__global__ void zero_kernel() {
    int i = blockIdx.x * blockDim.x + threadIdx.x;
    if (i < NN) { g_deg[i] = 0; g_cursor[i] = 0; }
}

__global__ void deg_kernel(const int* __restrict__ dst, int E) {
    int e = blockIdx.x * blockDim.x + threadIdx.x;
    if (e < E) atomicAdd(&g_deg[dst[e]], 1);
}

// fused norm + exclusive scan (single block, warp-shuffle hierarchy)
__global__ __launch_bounds__(1024) void normscan_kernel() {
    int tid = threadIdx.x;
    int lane = tid & 31, wid = tid >> 5;
    int vals[12];
    int base = tid * 12;
    int s = 0;
    #pragma unroll
    for (int j = 0; j < 12; j++) { vals[j] = g_deg[base + j]; s += vals[j]; }
    int x = s;
    #pragma unroll
    for (int o = 1; o < 32; o <<= 1) {
        int y = __shfl_up_sync(0xffffffffu, x, o);
        if (lane >= o) x += y;
    }
    __shared__ int wsum[32];
    if (lane == 31) wsum[wid] = x;
    __syncthreads();
    if (wid == 0) {
        int w = wsum[lane];
        #pragma unroll
        for (int o = 1; o < 32; o <<= 1) {
            int y = __shfl_up_sync(0xffffffffu, w, o);
            if (lane >= o) w += y;
        }
        wsum[lane] = w;
    }
    __syncthreads();
    int run = x - s + (wid ? wsum[wid - 1] : 0);
    #pragma unroll
    for (int j = 0; j < 12; j++) { g_offs[base + j] = run; run += vals[j]; }
    if (tid == 1023) g_offs[NN] = run;
    for (int i = tid; i < NN; i += 1024) {
        int d = g_deg[i];
        g_norm[i] = rsqrtf((float)(d > 0 ? d : 1));
    }
}

__global__ void fill_kernel(const int* __restrict__ src, const int* __restrict__ dst, int E) {
    int e = blockIdx.x * blockDim.x + threadIdx.x;
    if (e < E) {
        int d = dst[e];
        int s = src[e];
        int p = g_offs[d] + atomicAdd(&g_cursor[d], 1);
        g_csr_src[p] = s;
        g_csr_w[p]   = g_norm[s] * g_norm[d];
    }
}

// ---------------- SpMM hop: fp16 gather over CSR, fp32 accumulate ----------
// Inner loop batches 4 independent row loads for MLP.
__global__ void hop_kernel(int col_in, int col_out) {
    int v = blockIdx.x;
    int t = threadIdx.x;
    int s0 = g_offs[v], s1 = g_offs[v + 1];
    __shared__ int   s_src[256];
    __shared__ float s_w[256];
    float a0 = 0.f, a1 = 0.f;
    for (int base = s0; base < s1; base += 256) {
        int n = min(256, s1 - base);
        __syncthreads();
        if (t < n) { s_src[t] = g_csr_src[base + t]; s_w[t] = g_csr_w[base + t]; }
        __syncthreads();
        int i = 0;
        for (; i + 4 <= n; i += 4) {
            const __half2* r0 = reinterpret_cast<const __half2*>(
                g_Fh + (size_t)s_src[i + 0] * LDF + col_in);
            const __half2* r1 = reinterpret_cast<const __half2*>(
                g_Fh + (size_t)s_src[i + 1] * LDF + col_in);
            const __half2* r2 = reinterpret_cast<const __half2*>(
                g_Fh + (size_t)s_src[i + 2] * LDF + col_in);
            const __half2* r3 = reinterpret_cast<const __half2*>(
                g_Fh + (size_t)s_src[i + 3] * LDF + col_in);
            __half2 q0 = r0[t], q1 = r1[t], q2 = r2[t], q3 = r3[t];
            float w0 = s_w[i + 0], w1 = s_w[i + 1], w2 = s_w[i + 2], w3 = s_w[i + 3];
            float2 p0 = __half22float2(q0), p1 = __half22float2(q1);
            float2 p2 = __half22float2(q2), p3 = __half22float2(q3);
            a0 += w0 * p0.x + w1 * p1.x + w2 * p2.x + w3 * p3.x;
            a1 += w0 * p0.y + w1 * p1.y + w2 * p2.y + w3 * p3.y;
        }
        for (; i < n; i++) {
            const __half2* row = reinterpret_cast<const __half2*>(
                g_Fh + (size_t)s_src[i] * LDF + col_in);
            float w = s_w[i];
            float2 p = __half22float2(row[t]);
            a0 += w * p.x;
            a1 += w * p.y;
        }
    }
    *reinterpret_cast<__half2*>(g_Fh + (size_t)v * LDF + col_out + 2 * t) =
        __floats2half2_rn(a0, a1);
}

// ---------------- fp32 -> fp16 convert: d_sim and m_sim in one launch ------
#define ND4 (N_D * N_D / 4)
#define NM4 (N_M * N_M / 4)
__global__ void cvtA_all(const float* __restrict__ Ad, const float* __restrict__ Am,
                         __half* __restrict__ out)
{
    int i = blockIdx.x * blockDim.x + threadIdx.x;
    const float* A; size_t o4;
    if (i < ND4) { A = Ad; o4 = (size_t)i; }
    else if (i < ND4 + NM4) { A = Am; o4 = i - ND4; }
    else return;
    float4 v = reinterpret_cast<const float4*>(A)[o4];
    uint2 p;
    __half2* hp = reinterpret_cast<__half2*>(&p);
    hp[0] = __floats2half2_rn(v.x, v.y);
    hp[1] = __floats2half2_rn(v.z, v.w);
    reinterpret_cast<uint2*>(out)[i] = p;
}

// ---------------- fused weight transpose: Wd|Wm|Wf -> [512,K] fp16 ----------
__global__ void cvtBT_all(const float* __restrict__ Wd, const float* __restrict__ Wm,
                          const float* __restrict__ Wf, __half* __restrict__ o)
{
    const float* W; int K; size_t offs;
    int z = blockIdx.z;
    if (z == 0)      { W = Wd; K = N_D; offs = 0; }
    else if (z == 1) { W = Wm; K = N_M; offs = (size_t)512 * N_D; }
    else             { W = Wf; K = LDF; offs = (size_t)512 * (N_D + N_M); }
    int k0 = blockIdx.y * 32;
    if (k0 >= K) return;

    __shared__ float t[32][33];
    int n0 = blockIdx.x * 32;
    int tx = threadIdx.x, ty = threadIdx.y;  // 32 x 8
    #pragma unroll
    for (int r = 0; r < 32; r += 8)
        t[ty + r][tx] = W[(size_t)(k0 + ty + r) * HIDD + n0 + tx];
    __syncthreads();
    #pragma unroll
    for (int r = 0; r < 32; r += 8)
        o[offs + (size_t)(n0 + ty + r) * K + k0 + tx] = __float2half_rn(t[tx][ty + r]);
}

// ---------------- fp16 HMMA GEMM core ---------------------------------------
// 128x128 tile, 256 threads, BK=32, 5-stage cp.async, 2 CTAs/SM.
// mode 0 (dm): by<128 -> m piece (mblk=by>>1, kp=by&1, K-half 4096 -> g_Pm);
//              by>=128 -> d piece (p=by-128, mblk=p>>3, kp=p&7, K=512 -> g_Pd).
//              m pieces at low bids -> scheduled first (LPT).
// mode 1 (f):  by in [0,192): rb=by%96, kp=by/96; K=1280 half -> g_Pf.
#define GSTG 5
#define TILE_B   8192                  // one 128x32 fp16 tile
#define STAGE_B2 (2 * TILE_B)          // A + B per stage = 16 KB
#define GEMM_SMEM (GSTG * STAGE_B2)    // 80 KB

__global__ __launch_bounds__(256, 2) void gemm_core(
    const __half* __restrict__ Aall, const __half* __restrict__ Bt, int mode)
{
    extern __shared__ char dynsm[];
    const uint32_t sbase = smem_u32(dynsm);

    const int tid = threadIdx.x;
    const int wid = tid >> 5;
    const int lid = tid & 31;
    const int wm  = wid >> 1;
    const int wn  = wid & 1;
    const int by  = blockIdx.y;
    const int nb0 = blockIdx.x * 128;

    const __half* A; const __half* Bh;
    int Kst, chunks;
    __half* outp;
    if (mode == 0) {
        if (by < 128) {                 // m split-K x2
            int mblk = by >> 1, kp = by & 1;
            A   = Aall + (size_t)N_D * N_D + (size_t)mblk * 128 * N_M + kp * 4096;
            Kst = N_M; chunks = 4096 >> 5;
            Bh  = Bt + (size_t)512 * N_D + (size_t)nb0 * N_M + kp * 4096;
            outp = g_Pm + (size_t)kp * N_M * HIDD
                 + (size_t)mblk * 128 * HIDD + nb0;
        } else {                        // d split-K x8
            int p = by - 128, mblk = p >> 3, kp = p & 7;
            A   = Aall + (size_t)mblk * 128 * N_D + kp * 512;
            Kst = N_D; chunks = 512 >> 5;
            Bh  = Bt + (size_t)nb0 * N_D + kp * 512;
            outp = g_Pd + (size_t)kp * N_D * HIDD
                 + (size_t)mblk * 128 * HIDD + nb0;
        }
    } else {
        int rb = by % 96, kp = by / 96;
        A   = g_Fh + (size_t)rb * 128 * LDF + kp * 1280;
        Kst = LDF; chunks = 1280 >> 5;
        Bh  = Bt + (size_t)512 * (N_D + N_M) + (size_t)nb0 * LDF + kp * 1280;
        outp = g_Pf + (size_t)kp * NN * HIDD + (size_t)rb * 128 * HIDD + nb0;
    }

    auto load_stage = [&](int stage, int c) {
        const int k0 = c << 5;
        const uint32_t sb = sbase + stage * STAGE_B2;
        #pragma unroll
        for (int i = 0; i < 2; i++) {
            int idx = tid + (i << 8);
            int row = idx >> 2, ch = idx & 3;
            uint32_t sw = (uint32_t)(ch ^ ((row >> 1) & 3));
            uint32_t off = row * 64 + (sw << 4);
            cpasync16(sb + off,          A  + (size_t)row * Kst + k0 + ch * 8);
            cpasync16(sb + TILE_B + off, Bh + (size_t)row * Kst + k0 + ch * 8);
        }
    };
    auto ldfrags = [&](uint32_t sb, int ks, uint32_t (*aF)[4], uint32_t (*bF)[2]) {
        #pragma unroll
        for (int mt = 0; mt < 2; mt++) {
            int row = wm * 32 + mt * 16 + (lid & 15);
            int ch  = ks * 2 + (lid >> 4);
            uint32_t off = row * 64 + ((uint32_t)(ch ^ ((row >> 1) & 3)) << 4);
            ldsm_x4(sb + off, aF[mt][0], aF[mt][1], aF[mt][2], aF[mt][3]);
        }
        #pragma unroll
        for (int nt2 = 0; nt2 < 4; nt2++) {
            int row = wn * 64 + nt2 * 16 + (lid & 7) + ((lid >> 4) << 3);
            int ch  = ks * 2 + ((lid >> 3) & 1);
            uint32_t off = row * 64 + ((uint32_t)(ch ^ ((row >> 1) & 3)) << 4);
            ldsm_x4(sb + TILE_B + off,
                    bF[2*nt2][0], bF[2*nt2][1], bF[2*nt2+1][0], bF[2*nt2+1][1]);
        }
    };

    float acc[2][8][4] = {};

    #pragma unroll
    for (int s = 0; s < GSTG - 1; s++) { load_stage(s, s); cp_commit(); }

    for (int c = 0; c < chunks; c++) {
        cp_wait<GSTG - 2>();
        __syncthreads();
        const int cl = c + GSTG - 1;
        if (cl < chunks) load_stage(cl % GSTG, cl);
        cp_commit();

        const uint32_t sb = sbase + (c % GSTG) * STAGE_B2;
        #pragma unroll
        for (int ks = 0; ks < 2; ks++) {
            uint32_t aF[2][4], bF[8][2];
            ldfrags(sb, ks, aF, bF);
            #pragma unroll
            for (int mt = 0; mt < 2; mt++)
                #pragma unroll
                for (int nt = 0; nt < 8; nt++)
                    mma16816(acc[mt][nt], aF[mt], bF[nt]);
        }
    }

    // ---- epilogue: fp16 partials to outp (row stride HIDD)
    const int gid = lid >> 2, tig = lid & 3;
    #pragma unroll
    for (int mt = 0; mt < 2; mt++) {
        #pragma unroll
        for (int nt = 0; nt < 8; nt++) {
            int r0  = wm * 32 + mt * 16 + gid;
            int col = wn * 64 + nt * 8 + tig * 2;
            *reinterpret_cast<__half2*>(outp + (size_t)r0 * HIDD + col) =
                __floats2half2_rn(acc[mt][nt][0], acc[mt][nt][1]);
            *reinterpret_cast<__half2*>(outp + (size_t)(r0 + 8) * HIDD + col) =
                __floats2half2_rn(acc[mt][nt][2], acc[mt][nt][3]);
        }
    }
}

// ---------------- fixup: sum split-K partials into Fh -----------------------
__global__ void fixup_dm() {
    int i = blockIdx.x * 256 + threadIdx.x;          // over NN*HIDD/2 half2
    if (i >= NN * HIDD / 2) return;
    int row = i / (HIDD / 2), c2 = i % (HIDD / 2);
    float2 s = make_float2(0.f, 0.f);
    if (row < N_D) {
        const __half2* P = reinterpret_cast<const __half2*>(g_Pd);
        size_t base = (size_t)row * (HIDD / 2) + c2;
        #pragma unroll
        for (int kp = 0; kp < 8; kp++) {
            float2 v = __half22float2(P[(size_t)kp * (N_D * HIDD / 2) + base]);
            s.x += v.x; s.y += v.y;
        }
    } else {
        const __half2* P = reinterpret_cast<const __half2*>(g_Pm);
        size_t base = (size_t)(row - N_D) * (HIDD / 2) + c2;
        #pragma unroll
        for (int kp = 0; kp < 2; kp++) {
            float2 v = __half22float2(P[(size_t)kp * (N_M * HIDD / 2) + base]);
            s.x += v.x; s.y += v.y;
        }
    }
    *reinterpret_cast<__half2*>(g_Fh + (size_t)row * LDF + 2 * c2) =
        __floats2half2_rn(s.x, s.y);
}

__global__ void fixup_f(const float* __restrict__ bias) {
    int i = blockIdx.x * 256 + threadIdx.x;          // over NN*HIDD/2 half2
    if (i >= NN * HIDD / 2) return;
    const __half2* P = reinterpret_cast<const __half2*>(g_Pf);
    float2 a = __half22float2(P[i]);
    float2 b = __half22float2(P[(size_t)(NN * HIDD / 2) + i]);
    int c2 = i % (HIDD / 2);
    float2 bb = *reinterpret_cast<const float2*>(bias + 2 * c2);
    reinterpret_cast<__half2*>(g_hh)[i] =
        __floats2half2_rn(a.x + b.x + bb.x, a.y + b.y + bb.y);
}

// ---------------- pair scoring: warp per pair, fp16 h -----------------------
__global__ void pair_kernel(const int* __restrict__ dis, const int* __restrict__ mir,
                            const float* __restrict__ Wp, const float* __restrict__ bp,
                            float* __restrict__ out, int P)
{
    int warp = (blockIdx.x * blockDim.x + threadIdx.x) >> 5;
    int lane = threadIdx.x & 31;
    if (warp >= P) return;
    int di = dis[warp];
    int mi = mir[warp];
    const __half2* hd = reinterpret_cast<const __half2*>(g_hh + (size_t)di * HIDD);
    const __half2* hm = reinterpret_cast<const __half2*>(g_hh + (size_t)mi * HIDD);
    float s = 0.f;
    #pragma unroll 4
    for (int c2 = lane; c2 < HIDD / 2; c2 += 32) {
        float2 a = __half22float2(hd[c2]);
        float2 b = __half22float2(hm[c2]);
        int c = 2 * c2;
        s += a.x * Wp[c]     + b.x * Wp[HIDD + c]     + (a.x * b.x) * Wp[2 * HIDD + c];
        s += a.y * Wp[c + 1] + b.y * Wp[HIDD + c + 1] + (a.y * b.y) * Wp[2 * HIDD + c + 1];
    }
    #pragma unroll
    for (int o = 16; o; o >>= 1) s += __shfl_xor_sync(0xffffffffu, s, o);
    if (lane == 0) out[warp] = 1.f / (1.f + expf(-(s + bp[0])));
}

// ---------------- launch ----------------------------------------------------
extern "C" void kernel_launch(void* const* d_in, const int* in_sizes, int n_in,
                              void* d_out, int out_size)
{
    const float* d_sim    = (const float*)d_in[0];
    const float* m_sim    = (const float*)d_in[1];
    const int*   src      = (const int*)  d_in[2];
    const int*   dst      = (const int*)  d_in[3];
    const int*   diseases = (const int*)  d_in[4];
    const int*   mirnas   = (const int*)  d_in[5];
    const float* Wd       = (const float*)d_in[6];
    const float* Wm       = (const float*)d_in[7];
    const float* Wf       = (const float*)d_in[8];
    const float* bf       = (const float*)d_in[9];
    const float* Wp       = (const float*)d_in[10];
    const float* bp       = (const float*)d_in[11];
    float*       out      = (float*)d_out;

    const int E = in_sizes[2];
    const int P = in_sizes[4];

    __half *Bt = nullptr, *Ah = nullptr;
    cudaGetSymbolAddress((void**)&Bt, g_Bt);
    cudaGetSymbolAddress((void**)&Ah, g_Ah);

    cudaFuncSetAttribute(gemm_core, cudaFuncAttributeMaxDynamicSharedMemorySize, GEMM_SMEM);

    // launches ordered so gemm_core(dm) is #4 (the one ncu profiles)
    cvtA_all<<<(ND4 + NM4 + 255) / 256, 256>>>(d_sim, m_sim, Ah);               // 1
    cvtBT_all<<<dim3(HIDD / 32, N_M / 32, 3), dim3(32, 8)>>>(Wd, Wm, Wf, Bt);   // 2
    zero_kernel<<<(NN + 255) / 256, 256>>>();                                   // 3
    gemm_core<<<dim3(4, 384), 256, GEMM_SMEM>>>(Ah, Bt, 0);                     // 4 <- profiled
    fixup_dm<<<(NN * HIDD / 2 + 255) / 256, 256>>>();                           // 5
    deg_kernel<<<(E + 255) / 256, 256>>>(dst, E);                               // 6
    normscan_kernel<<<1, 1024>>>();                                             // 7
    fill_kernel<<<(E + 255) / 256, 256>>>(src, dst, E);                         // 8

    // ---- K hops of normalized gather-sum (fp16 feat, fp32 accumulate)
    for (int hop = 0; hop < KHOP; hop++)
        hop_kernel<<<NN, 256>>>(hop * HIDD, (hop + 1) * HIDD);

    // ---- h = feat @ Wf + bf  (split-K x2, fp16 partials, fixup adds bias)
    gemm_core<<<dim3(4, 192), 256, GEMM_SMEM>>>(nullptr, Bt, 1);
    fixup_f<<<(NN * HIDD / 2 + 255) / 256, 256>>>(bf);

    // ---- pair prediction with sigmoid
    pair_kernel<<<(P * 32 + 255) / 256, 256>>>(diseases, mirnas, Wp, bp, out, P);
    (void)n_in; (void)out_size;
}

// round 15
// speedup vs baseline: 1.0275x; 1.0275x over previous
#include <cuda_runtime.h>
#include <cuda_fp16.h>
#include <math.h>
#include <stdint.h>

// Problem constants (fixed shapes per reference)
#define N_D   4096
#define N_M   8192
#define NN    12288          // N_D + N_M
#define EE    196608
#define KHOP  4
#define HIDD  512
#define LDF   2560           // HID*(K+1)

// ---------------- device scratch ------------------------------------------
__device__ int   g_deg[NN];
__device__ float g_norm[NN];
__device__ int   g_offs[NN + 1];
__device__ int   g_cursor[NN];
__device__ int   g_csr_src[EE];
__device__ float g_csr_w[EE];
__device__ __half g_hh[(size_t)NN * HIDD];                // [N, 512] fp16 h
__device__ __half g_Fh[(size_t)NN * LDF];                 // feat, fp16
__device__ __half g_Bt[(size_t)512 * (N_D + N_M + LDF)];  // W^T fp16 (d|m|f)
__device__ __half g_Ah[(size_t)N_D * N_D + (size_t)N_M * N_M]; // fp16 sims (d|m)
__device__ __half g_Pd[(size_t)8 * N_D * HIDD];           // d split-K partials (x8)
__device__ __half g_Pm[(size_t)2 * N_M * HIDD];           // m split-K partials (x2)

// ---------------- PTX helpers (plain sm_103-safe) ---------------------------
__device__ __forceinline__ uint32_t smem_u32(const void* p) {
    uint32_t a;
    asm("{ .reg .u64 t; cvta.to.shared.u64 t, %1; cvt.u32.u64 %0, t; }"
        : "=r"(a) : "l"(p));
    return a;
}

__device__ __forceinline__ void cpasync16(uint32_t dst, const void* src) {
    asm volatile("cp.async.cg.shared.global [%0], [%1], 16;" :: "r"(dst), "l"(src));
}
__device__ __forceinline__ void cp_commit() {
    asm volatile("cp.async.commit_group;" ::: "memory");
}
template <int N>
__device__ __forceinline__ void cp_wait() {
    asm volatile("cp.async.wait_group %0;" :: "n"(N) : "memory");
}

__device__ __forceinline__ void ldsm_x4(uint32_t addr, uint32_t& r0, uint32_t& r1,
                                        uint32_t& r2, uint32_t& r3) {
    asm volatile("ldmatrix.sync.aligned.m8n8.x4.shared.b16 {%0,%1,%2,%3}, [%4];"
                 : "=r"(r0), "=r"(r1), "=r"(r2), "=r"(r3) : "r"(addr));
}

__device__ __forceinline__ void mma16816(float* c, const uint32_t* a, const uint32_t* b) {
    asm volatile(
        "mma.sync.aligned.m16n8k16.row.col.f32.f16.f16.f32 "
        "{%0,%1,%2,%3}, {%4,%5,%6,%7}, {%8,%9}, {%0,%1,%2,%3};"
        : "+f"(c[0]), "+f"(c[1]), "+f"(c[2]), "+f"(c[3])
        : "r"(a[0]), "r"(a[1]), "r"(a[2]), "r"(a[3]), "r"(b[0]), "r"(b[1]));
}

// ---------------- graph-prep kernels ---------------------------------------
__global__ void zero_kernel() {
    int i = blockIdx.x * blockDim.x + threadIdx.x;
    if (i < NN) { g_deg[i] = 0; g_cursor[i] = 0; }
}

__global__ void deg_kernel(const int* __restrict__ dst, int E) {
    int e = blockIdx.x * blockDim.x + threadIdx.x;
    if (e < E) atomicAdd(&g_deg[dst[e]], 1);
}

// fused norm + exclusive scan (single block, warp-shuffle hierarchy)
__global__ __launch_bounds__(1024) void normscan_kernel() {
    int tid = threadIdx.x;
    int lane = tid & 31, wid = tid >> 5;
    int vals[12];
    int base = tid * 12;
    int s = 0;
    #pragma unroll
    for (int j = 0; j < 12; j++) { vals[j] = g_deg[base + j]; s += vals[j]; }
    int x = s;
    #pragma unroll
    for (int o = 1; o < 32; o <<= 1) {
        int y = __shfl_up_sync(0xffffffffu, x, o);
        if (lane >= o) x += y;
    }
    __shared__ int wsum[32];
    if (lane == 31) wsum[wid] = x;
    __syncthreads();
    if (wid == 0) {
        int w = wsum[lane];
        #pragma unroll
        for (int o = 1; o < 32; o <<= 1) {
            int y = __shfl_up_sync(0xffffffffu, w, o);
            if (lane >= o) w += y;
        }
        wsum[lane] = w;
    }
    __syncthreads();
    int run = x - s + (wid ? wsum[wid - 1] : 0);
    #pragma unroll
    for (int j = 0; j < 12; j++) { g_offs[base + j] = run; run += vals[j]; }
    if (tid == 1023) g_offs[NN] = run;
    for (int i = tid; i < NN; i += 1024) {
        int d = g_deg[i];
        g_norm[i] = rsqrtf((float)(d > 0 ? d : 1));
    }
}

__global__ void fill_kernel(const int* __restrict__ src, const int* __restrict__ dst, int E) {
    int e = blockIdx.x * blockDim.x + threadIdx.x;
    if (e < E) {
        int d = dst[e];
        int s = src[e];
        int p = g_offs[d] + atomicAdd(&g_cursor[d], 1);
        g_csr_src[p] = s;
        g_csr_w[p]   = g_norm[s] * g_norm[d];
    }
}

// ---------------- SpMM hop: fp16 gather over CSR, fp32 accumulate ----------
__global__ void hop_kernel(int col_in, int col_out) {
    int v = blockIdx.x;
    int t = threadIdx.x;
    int s0 = g_offs[v], s1 = g_offs[v + 1];
    __shared__ int   s_src[256];
    __shared__ float s_w[256];
    float a0 = 0.f, a1 = 0.f;
    for (int base = s0; base < s1; base += 256) {
        int n = min(256, s1 - base);
        __syncthreads();
        if (t < n) { s_src[t] = g_csr_src[base + t]; s_w[t] = g_csr_w[base + t]; }
        __syncthreads();
        int i = 0;
        for (; i + 4 <= n; i += 4) {
            const __half2* r0 = reinterpret_cast<const __half2*>(
                g_Fh + (size_t)s_src[i + 0] * LDF + col_in);
            const __half2* r1 = reinterpret_cast<const __half2*>(
                g_Fh + (size_t)s_src[i + 1] * LDF + col_in);
            const __half2* r2 = reinterpret_cast<const __half2*>(
                g_Fh + (size_t)s_src[i + 2] * LDF + col_in);
            const __half2* r3 = reinterpret_cast<const __half2*>(
                g_Fh + (size_t)s_src[i + 3] * LDF + col_in);
            __half2 q0 = r0[t], q1 = r1[t], q2 = r2[t], q3 = r3[t];
            float w0 = s_w[i + 0], w1 = s_w[i + 1], w2 = s_w[i + 2], w3 = s_w[i + 3];
            float2 p0 = __half22float2(q0), p1 = __half22float2(q1);
            float2 p2 = __half22float2(q2), p3 = __half22float2(q3);
            a0 += w0 * p0.x + w1 * p1.x + w2 * p2.x + w3 * p3.x;
            a1 += w0 * p0.y + w1 * p1.y + w2 * p2.y + w3 * p3.y;
        }
        for (; i < n; i++) {
            const __half2* row = reinterpret_cast<const __half2*>(
                g_Fh + (size_t)s_src[i] * LDF + col_in);
            float w = s_w[i];
            float2 p = __half22float2(row[t]);
            a0 += w * p.x;
            a1 += w * p.y;
        }
    }
    *reinterpret_cast<__half2*>(g_Fh + (size_t)v * LDF + col_out + 2 * t) =
        __floats2half2_rn(a0, a1);
}

// ---------------- fp32 -> fp16 convert: d_sim and m_sim in one launch ------
#define ND4 (N_D * N_D / 4)
#define NM4 (N_M * N_M / 4)
__global__ void cvtA_all(const float* __restrict__ Ad, const float* __restrict__ Am,
                         __half* __restrict__ out)
{
    int i = blockIdx.x * blockDim.x + threadIdx.x;
    const float* A; size_t o4;
    if (i < ND4) { A = Ad; o4 = (size_t)i; }
    else if (i < ND4 + NM4) { A = Am; o4 = i - ND4; }
    else return;
    float4 v = reinterpret_cast<const float4*>(A)[o4];
    uint2 p;
    __half2* hp = reinterpret_cast<__half2*>(&p);
    hp[0] = __floats2half2_rn(v.x, v.y);
    hp[1] = __floats2half2_rn(v.z, v.w);
    reinterpret_cast<uint2*>(out)[i] = p;
}

// ---------------- fused weight transpose: Wd|Wm|Wf -> [512,K] fp16 ----------
__global__ void cvtBT_all(const float* __restrict__ Wd, const float* __restrict__ Wm,
                          const float* __restrict__ Wf, __half* __restrict__ o)
{
    const float* W; int K; size_t offs;
    int z = blockIdx.z;
    if (z == 0)      { W = Wd; K = N_D; offs = 0; }
    else if (z == 1) { W = Wm; K = N_M; offs = (size_t)512 * N_D; }
    else             { W = Wf; K = LDF; offs = (size_t)512 * (N_D + N_M); }
    int k0 = blockIdx.y * 32;
    if (k0 >= K) return;

    __shared__ float t[32][33];
    int n0 = blockIdx.x * 32;
    int tx = threadIdx.x, ty = threadIdx.y;  // 32 x 8
    #pragma unroll
    for (int r = 0; r < 32; r += 8)
        t[ty + r][tx] = W[(size_t)(k0 + ty + r) * HIDD + n0 + tx];
    __syncthreads();
    #pragma unroll
    for (int r = 0; r < 32; r += 8)
        o[offs + (size_t)(n0 + ty + r) * K + k0 + tx] = __float2half_rn(t[tx][ty + r]);
}

// ---------------- fp16 HMMA GEMM core ---------------------------------------
// 128x128 tile, 256 threads, BK=32, 5-stage cp.async, 2 CTAs/SM.
// mode 0 (dm): by<128 -> m piece (mblk=by>>1, kp=by&1, K-half 4096 -> g_Pm);
//              by>=128 -> d piece (p=by-128, mblk=p>>3, kp=p&7, K=512 -> g_Pd).
// mode 1 (f):  by in [0,96): full K=2560, fp16 out to g_hh with bias.
#define GSTG 5
#define TILE_B   8192                  // one 128x32 fp16 tile
#define STAGE_B2 (2 * TILE_B)          // A + B per stage = 16 KB
#define GEMM_SMEM (GSTG * STAGE_B2)    // 80 KB

__global__ __launch_bounds__(256, 2) void gemm_core(
    const __half* __restrict__ Aall, const __half* __restrict__ Bt,
    const float* __restrict__ bias, int mode)
{
    extern __shared__ char dynsm[];
    const uint32_t sbase = smem_u32(dynsm);

    const int tid = threadIdx.x;
    const int wid = tid >> 5;
    const int lid = tid & 31;
    const int wm  = wid >> 1;
    const int wn  = wid & 1;
    const int by  = blockIdx.y;
    const int nb0 = blockIdx.x * 128;

    const __half* A; const __half* Bh;
    int Kst, chunks, ostr;
    __half* outp;
    const float* biasp = nullptr;
    if (mode == 0) {
        ostr = HIDD;
        if (by < 128) {                 // m split-K x2
            int mblk = by >> 1, kp = by & 1;
            A   = Aall + (size_t)N_D * N_D + (size_t)mblk * 128 * N_M + kp * 4096;
            Kst = N_M; chunks = 4096 >> 5;
            Bh  = Bt + (size_t)512 * N_D + (size_t)nb0 * N_M + kp * 4096;
            outp = g_Pm + (size_t)kp * N_M * HIDD
                 + (size_t)mblk * 128 * HIDD + nb0;
        } else {                        // d split-K x8
            int p = by - 128, mblk = p >> 3, kp = p & 7;
            A   = Aall + (size_t)mblk * 128 * N_D + kp * 512;
            Kst = N_D; chunks = 512 >> 5;
            Bh  = Bt + (size_t)nb0 * N_D + kp * 512;
            outp = g_Pd + (size_t)kp * N_D * HIDD
                 + (size_t)mblk * 128 * HIDD + nb0;
        }
    } else {                            // f: full K, bias, out g_hh
        ostr = HIDD;
        A   = g_Fh + (size_t)by * 128 * LDF;
        Kst = LDF; chunks = LDF >> 5;
        Bh  = Bt + (size_t)512 * (N_D + N_M) + (size_t)nb0 * LDF;
        outp = g_hh + (size_t)by * 128 * HIDD + nb0;
        biasp = bias + nb0;
    }

    auto load_stage = [&](int stage, int c) {
        const int k0 = c << 5;
        const uint32_t sb = sbase + stage * STAGE_B2;
        #pragma unroll
        for (int i = 0; i < 2; i++) {
            int idx = tid + (i << 8);
            int row = idx >> 2, ch = idx & 3;
            uint32_t sw = (uint32_t)(ch ^ ((row >> 1) & 3));
            uint32_t off = row * 64 + (sw << 4);
            cpasync16(sb + off,          A  + (size_t)row * Kst + k0 + ch * 8);
            cpasync16(sb + TILE_B + off, Bh + (size_t)row * Kst + k0 + ch * 8);
        }
    };
    auto ldfrags = [&](uint32_t sb, int ks, uint32_t (*aF)[4], uint32_t (*bF)[2]) {
        #pragma unroll
        for (int mt = 0; mt < 2; mt++) {
            int row = wm * 32 + mt * 16 + (lid & 15);
            int ch  = ks * 2 + (lid >> 4);
            uint32_t off = row * 64 + ((uint32_t)(ch ^ ((row >> 1) & 3)) << 4);
            ldsm_x4(sb + off, aF[mt][0], aF[mt][1], aF[mt][2], aF[mt][3]);
        }
        #pragma unroll
        for (int nt2 = 0; nt2 < 4; nt2++) {
            int row = wn * 64 + nt2 * 16 + (lid & 7) + ((lid >> 4) << 3);
            int ch  = ks * 2 + ((lid >> 3) & 1);
            uint32_t off = row * 64 + ((uint32_t)(ch ^ ((row >> 1) & 3)) << 4);
            ldsm_x4(sb + TILE_B + off,
                    bF[2*nt2][0], bF[2*nt2][1], bF[2*nt2+1][0], bF[2*nt2+1][1]);
        }
    };

    float acc[2][8][4] = {};

    #pragma unroll
    for (int s = 0; s < GSTG - 1; s++) { load_stage(s, s); cp_commit(); }

    for (int c = 0; c < chunks; c++) {
        cp_wait<GSTG - 2>();
        __syncthreads();
        const int cl = c + GSTG - 1;
        if (cl < chunks) load_stage(cl % GSTG, cl);
        cp_commit();

        const uint32_t sb = sbase + (c % GSTG) * STAGE_B2;
        #pragma unroll
        for (int ks = 0; ks < 2; ks++) {
            uint32_t aF[2][4], bF[8][2];
            ldfrags(sb, ks, aF, bF);
            #pragma unroll
            for (int mt = 0; mt < 2; mt++)
                #pragma unroll
                for (int nt = 0; nt < 8; nt++)
                    mma16816(acc[mt][nt], aF[mt], bF[nt]);
        }
    }

    // ---- epilogue: fp16 to outp (+ optional bias for mode 1)
    const int gid = lid >> 2, tig = lid & 3;
    #pragma unroll
    for (int mt = 0; mt < 2; mt++) {
        #pragma unroll
        for (int nt = 0; nt < 8; nt++) {
            int r0  = wm * 32 + mt * 16 + gid;
            int col = wn * 64 + nt * 8 + tig * 2;
            float2 v0 = make_float2(acc[mt][nt][0], acc[mt][nt][1]);
            float2 v1 = make_float2(acc[mt][nt][2], acc[mt][nt][3]);
            if (biasp) {
                float2 bb = *reinterpret_cast<const float2*>(biasp + col);
                v0.x += bb.x; v0.y += bb.y;
                v1.x += bb.x; v1.y += bb.y;
            }
            *reinterpret_cast<__half2*>(outp + (size_t)r0 * ostr + col) =
                __floats2half2_rn(v0.x, v0.y);
            *reinterpret_cast<__half2*>(outp + (size_t)(r0 + 8) * ostr + col) =
                __floats2half2_rn(v1.x, v1.y);
        }
    }
    if (mode == 0) ;  // keep branch structure minimal (outp stride shared)
}

// ---------------- fixup: sum split-K partials into Fh -----------------------
__global__ void fixup_dm() {
    int i = blockIdx.x * 256 + threadIdx.x;          // over NN*HIDD/2 half2
    if (i >= NN * HIDD / 2) return;
    int row = i / (HIDD / 2), c2 = i % (HIDD / 2);
    float2 s = make_float2(0.f, 0.f);
    if (row < N_D) {
        const __half2* P = reinterpret_cast<const __half2*>(g_Pd);
        size_t base = (size_t)row * (HIDD / 2) + c2;
        #pragma unroll
        for (int kp = 0; kp < 8; kp++) {
            float2 v = __half22float2(P[(size_t)kp * (N_D * HIDD / 2) + base]);
            s.x += v.x; s.y += v.y;
        }
    } else {
        const __half2* P = reinterpret_cast<const __half2*>(g_Pm);
        size_t base = (size_t)(row - N_D) * (HIDD / 2) + c2;
        #pragma unroll
        for (int kp = 0; kp < 2; kp++) {
            float2 v = __half22float2(P[(size_t)kp * (N_M * HIDD / 2) + base]);
            s.x += v.x; s.y += v.y;
        }
    }
    *reinterpret_cast<__half2*>(g_Fh + (size_t)row * LDF + 2 * c2) =
        __floats2half2_rn(s.x, s.y);
}

// ---------------- pair scoring: warp per pair, fp16 h -----------------------
__global__ void pair_kernel(const int* __restrict__ dis, const int* __restrict__ mir,
                            const float* __restrict__ Wp, const float* __restrict__ bp,
                            float* __restrict__ out, int P)
{
    int warp = (blockIdx.x * blockDim.x + threadIdx.x) >> 5;
    int lane = threadIdx.x & 31;
    if (warp >= P) return;
    int di = dis[warp];
    int mi = mir[warp];
    const __half2* hd = reinterpret_cast<const __half2*>(g_hh + (size_t)di * HIDD);
    const __half2* hm = reinterpret_cast<const __half2*>(g_hh + (size_t)mi * HIDD);
    float s = 0.f;
    #pragma unroll 4
    for (int c2 = lane; c2 < HIDD / 2; c2 += 32) {
        float2 a = __half22float2(hd[c2]);
        float2 b = __half22float2(hm[c2]);
        int c = 2 * c2;
        s += a.x * Wp[c]     + b.x * Wp[HIDD + c]     + (a.x * b.x) * Wp[2 * HIDD + c];
        s += a.y * Wp[c + 1] + b.y * Wp[HIDD + c + 1] + (a.y * b.y) * Wp[2 * HIDD + c + 1];
    }
    #pragma unroll
    for (int o = 16; o; o >>= 1) s += __shfl_xor_sync(0xffffffffu, s, o);
    if (lane == 0) out[warp] = 1.f / (1.f + expf(-(s + bp[0])));
}

// ---------------- launch ----------------------------------------------------
extern "C" void kernel_launch(void* const* d_in, const int* in_sizes, int n_in,
                              void* d_out, int out_size)
{
    const float* d_sim    = (const float*)d_in[0];
    const float* m_sim    = (const float*)d_in[1];
    const int*   src      = (const int*)  d_in[2];
    const int*   dst      = (const int*)  d_in[3];
    const int*   diseases = (const int*)  d_in[4];
    const int*   mirnas   = (const int*)  d_in[5];
    const float* Wd       = (const float*)d_in[6];
    const float* Wm       = (const float*)d_in[7];
    const float* Wf       = (const float*)d_in[8];
    const float* bf       = (const float*)d_in[9];
    const float* Wp       = (const float*)d_in[10];
    const float* bp       = (const float*)d_in[11];
    float*       out      = (float*)d_out;

    const int E = in_sizes[2];
    const int P = in_sizes[4];

    __half *Bt = nullptr, *Ah = nullptr;
    cudaGetSymbolAddress((void**)&Bt, g_Bt);
    cudaGetSymbolAddress((void**)&Ah, g_Ah);

    cudaFuncSetAttribute(gemm_core, cudaFuncAttributeMaxDynamicSharedMemorySize, GEMM_SMEM);

    // fork-join: prep chain runs on a second stream, overlapped with
    // cvtBT+cvtA+gemm on the default stream. Joined before the hops.
    cudaStream_t s2;
    cudaStreamCreateWithFlags(&s2, cudaStreamNonBlocking);
    cudaEvent_t e0, e2;
    cudaEventCreateWithFlags(&e0, cudaEventDisableTiming);
    cudaEventCreateWithFlags(&e2, cudaEventDisableTiming);

    cudaEventRecord(e0, 0);
    cudaStreamWaitEvent(s2, e0, 0);

    // s2: graph prep (independent of the GEMM pipeline)
    zero_kernel<<<(NN + 255) / 256, 256, 0, s2>>>();
    deg_kernel<<<(E + 255) / 256, 256, 0, s2>>>(dst, E);
    normscan_kernel<<<1, 1024, 0, s2>>>();
    fill_kernel<<<(E + 255) / 256, 256, 0, s2>>>(src, dst, E);
    cudaEventRecord(e2, s2);

    // default stream: conversions + feature GEMM + fixup
    cvtBT_all<<<dim3(HIDD / 32, N_M / 32, 3), dim3(32, 8)>>>(Wd, Wm, Wf, Bt);
    cvtA_all<<<(ND4 + NM4 + 255) / 256, 256>>>(d_sim, m_sim, Ah);
    gemm_core<<<dim3(4, 384), 256, GEMM_SMEM>>>(Ah, Bt, nullptr, 0);
    fixup_dm<<<(NN * HIDD / 2 + 255) / 256, 256>>>();

    // join: hops need the CSR (s2) and Fh (default)
    cudaStreamWaitEvent(0, e2, 0);

    // ---- K hops of normalized gather-sum (fp16 feat, fp32 accumulate)
    for (int hop = 0; hop < KHOP; hop++)
        hop_kernel<<<NN, 256>>>(hop * HIDD, (hop + 1) * HIDD);

    // ---- h = feat @ Wf + bf (full K, direct fp16 out, no fixup)
    gemm_core<<<dim3(4, 96), 256, GEMM_SMEM>>>(nullptr, Bt, bf, 1);

    // ---- pair prediction with sigmoid
    pair_kernel<<<(P * 32 + 255) / 256, 256>>>(diseases, mirnas, Wp, bp, out, P);
    (void)n_in; (void)out_size;
}